// round 15
// baseline (speedup 1.0000x reference)
#include <cuda_runtime.h>
#include <cuda_fp16.h>
#include <cstddef>
#include <cstdint>
#include <math_constants.h>

#define BB 8
#define CC 512
#define NHEADS 8
#define HD 64
#define NN 1024
#define NGROUPS 32
#define GSIZE ((CC / NGROUPS) * NN)   // 16384
#define EPSV 1e-5f

// ---------------- scratch ----------------
__device__ __half g_xn16[BB * CC * NN];        // 8 MB
__device__ __half g_qkv16[BB * 3 * CC * NN];   // 24 MB
__device__ __half g_ao16[BB * CC * NN];        // 8 MB
__device__ __half g_qw16[3 * CC * CC];         // 1.5 MB
__device__ __half g_pw16[CC * CC];             // 0.5 MB

// ---------------- helpers ----------------
__device__ __forceinline__ unsigned smem_u32(const void* p) {
    return (unsigned)__cvta_generic_to_shared(p);
}
__device__ __forceinline__ void cp16(void* sdst, const void* gsrc) {
    asm volatile("cp.async.cg.shared.global [%0], [%1], 16;\n"
                 :: "r"(smem_u32(sdst)), "l"(gsrc));
}
__device__ __forceinline__ void cp_commit() {
    asm volatile("cp.async.commit_group;\n");
}
template <int N>
__device__ __forceinline__ void cp_wait() {
    asm volatile("cp.async.wait_group %0;\n" :: "n"(N));
}
__device__ __forceinline__ void cp_arrive(unsigned mbar) {
    asm volatile("cp.async.mbarrier.arrive.noinc.shared.b64 [%0];\n"
                 :: "r"(mbar) : "memory");
}
#define MBAR_INIT(addr, cnt) \
    asm volatile("mbarrier.init.shared.b64 [%0], %1;" :: "r"(addr), "r"(cnt) : "memory")
#define MBAR_ARRIVE(addr) \
    asm volatile("mbarrier.arrive.shared.b64 _, [%0];" :: "r"(addr) : "memory")
#define MBAR_WAIT(addr, par) do {                                              \
    asm volatile("{\n\t.reg .pred P1;\n\t"                                     \
        "WAIT_%=:\n\t"                                                          \
        "mbarrier.try_wait.parity.acquire.cta.shared::cta.b64 P1, [%0], %1, 0x989680;\n\t" \
        "@P1 bra.uni DONE_%=;\n\t"                                              \
        "bra.uni WAIT_%=;\n\t"                                                  \
        "DONE_%=:\n\t}"                                                         \
        :: "r"(addr), "r"(par) : "memory");                                     \
} while (0)

__device__ __forceinline__ void ldsm_x4(unsigned& d0, unsigned& d1,
                                        unsigned& d2, unsigned& d3, const void* p) {
    asm volatile("ldmatrix.sync.aligned.m8n8.x4.shared.b16 {%0,%1,%2,%3}, [%4];\n"
                 : "=r"(d0), "=r"(d1), "=r"(d2), "=r"(d3) : "r"(smem_u32(p)));
}
__device__ __forceinline__ void ldsm_x4t(unsigned& d0, unsigned& d1,
                                         unsigned& d2, unsigned& d3, const void* p) {
    asm volatile("ldmatrix.sync.aligned.m8n8.x4.trans.shared.b16 {%0,%1,%2,%3}, [%4];\n"
                 : "=r"(d0), "=r"(d1), "=r"(d2), "=r"(d3) : "r"(smem_u32(p)));
}
__device__ __forceinline__ void mma_f16(float& c0, float& c1, float& c2, float& c3,
                                        unsigned a0, unsigned a1, unsigned a2, unsigned a3,
                                        unsigned b0, unsigned b1) {
    asm volatile(
        "mma.sync.aligned.m16n8k16.row.col.f32.f16.f16.f32 "
        "{%0,%1,%2,%3}, {%4,%5,%6,%7}, {%8,%9}, {%0,%1,%2,%3};\n"
        : "+f"(c0), "+f"(c1), "+f"(c2), "+f"(c3)
        : "r"(a0), "r"(a1), "r"(a2), "r"(a3), "r"(b0), "r"(b1));
}
__device__ __forceinline__ unsigned packh2(float lo, float hi) {
    unsigned u;
    asm("cvt.rn.f16x2.f32 %0, %2, %1;" : "=r"(u) : "f"(lo), "f"(hi));
    return u;
}
__device__ __forceinline__ unsigned h2exp2(unsigned x) {
    unsigned r;
    asm("ex2.approx.f16x2 %0, %1;" : "=r"(r) : "r"(x));
    return r;
}
__device__ __forceinline__ unsigned hsub2(unsigned a, unsigned b) {
    unsigned r;
    asm("sub.f16x2 %0, %1, %2;" : "=r"(r) : "r"(a), "r"(b));
    return r;
}
__device__ __forceinline__ unsigned hadd2(unsigned a, unsigned b) {
    unsigned r;
    asm("add.f16x2 %0, %1, %2;" : "=r"(r) : "r"(a), "r"(b));
    return r;
}
__device__ __forceinline__ float h2sum(unsigned x) {
    __half2 h = *(__half2*)&x;
    float2 f = __half22float2(h);
    return f.x + f.y;
}

// ---------------- weights f32 -> f16 ----------------
#define QW4 (3 * CC * CC / 4)
#define PW4 (CC * CC / 4)
__global__ void convert_weights(const float* __restrict__ qw, const float* __restrict__ pw,
                                __half* __restrict__ qw16, __half* __restrict__ pw16) {
    int i = blockIdx.x * blockDim.x + threadIdx.x;
    const float* src;
    __half* dst;
    int k;
    if (i < QW4) { src = qw; dst = qw16; k = i; }
    else if (i < QW4 + PW4) { src = pw; dst = pw16; k = i - QW4; }
    else return;
    float4 v = *(const float4*)&src[k * 4];
    __half2* o = (__half2*)&dst[k * 4];
    o[0] = __floats2half2_rn(v.x, v.y);
    o[1] = __floats2half2_rn(v.z, v.w);
}

// ---------------- GroupNorm: f32 in -> f16 out ----------------
__global__ void groupnorm_kernel(const float* __restrict__ x,
                                 const float* __restrict__ w,
                                 const float* __restrict__ bch,
                                 __half* __restrict__ xn) {
    int bg = blockIdx.x;
    const float* xp = x + (size_t)bg * GSIZE;
    __half* op = xn + (size_t)bg * GSIZE;
    int t = threadIdx.x;

    float s = 0.f, s2 = 0.f;
    for (int i = t; i < GSIZE / 4; i += blockDim.x) {
        float4 v = *(const float4*)&xp[i * 4];
        s  += v.x + v.y + v.z + v.w;
        s2 += v.x * v.x + v.y * v.y + v.z * v.z + v.w * v.w;
    }
    __shared__ float rs[32], rs2[32];
    for (int o = 16; o; o >>= 1) {
        s  += __shfl_xor_sync(0xffffffffu, s,  o);
        s2 += __shfl_xor_sync(0xffffffffu, s2, o);
    }
    if ((t & 31) == 0) { rs[t >> 5] = s; rs2[t >> 5] = s2; }
    __syncthreads();
    if (t < 32) {
        int nw = blockDim.x >> 5;
        float a  = (t < nw) ? rs[t]  : 0.f;
        float a2 = (t < nw) ? rs2[t] : 0.f;
        for (int o = 16; o; o >>= 1) {
            a  += __shfl_xor_sync(0xffffffffu, a,  o);
            a2 += __shfl_xor_sync(0xffffffffu, a2, o);
        }
        if (t == 0) {
            float mean = a / (float)GSIZE;
            float var  = a2 / (float)GSIZE - mean * mean;
            rs[0]  = mean;
            rs2[0] = rsqrtf(var + EPSV);
        }
    }
    __syncthreads();
    float mean = rs[0], rstd = rs2[0];
    int c0 = (bg % NGROUPS) * (CC / NGROUPS);
    for (int i = t; i < GSIZE / 4; i += blockDim.x) {
        int c = c0 + (i * 4) / NN;
        float sc = rstd * w[c], bc = bch[c] - mean * sc;
        float4 v = *(const float4*)&xp[i * 4];
        __half2* o = (__half2*)&op[i * 4];
        o[0] = __floats2half2_rn(v.x * sc + bc, v.y * sc + bc);
        o[1] = __floats2half2_rn(v.z * sc + bc, v.w * sc + bc);
    }
}

// ---------------- fp16 HGEMM, BK=64, 2-stage, one sync/iter ----------------
#define HBK 64
#define HA_LD 72
#define HB_LD 136
#define H_ABYTES (128 * HA_LD * 2)       // 18432
#define H_BBYTES (HBK * HB_LD * 2)       // 17408
#define H_STG (H_ABYTES + H_BBYTES)      // 35840
#define H_SMEM (2 * H_STG)               // 71680

template <bool HOUT>
__global__ __launch_bounds__(256, 2)
void hgemm(const __half* __restrict__ A,
           const __half* __restrict__ Bm,
           void* __restrict__ Cv,
           int K, int lda, int ldb, int ldc,
           long long sBi, long long sCi,
           const float* __restrict__ bias,
           const float* __restrict__ res,
           long long sRi) {
    int z = blockIdx.z;
    Bm += z * sBi;
    if (res) res += z * sRi;

    extern __shared__ __align__(16) char smc[];
    const int t  = threadIdx.x;
    const int w  = t >> 5, ln = t & 31;
    const int wr = w >> 2, wc = w & 3;
    const int i0 = blockIdx.x * 128, j0 = blockIdx.y * 128;

    auto load_stage = [&](int st, int k0) {
        char* Ad = smc + st * H_STG;
        char* Bd = Ad + H_ABYTES;
#pragma unroll
        for (int r = 0; r < 4; r++) {
            int idx = t + 256 * r;
            int row = idx >> 3, kc = idx & 7;
            cp16(Ad + row * (HA_LD * 2) + kc * 16,
                 &A[(size_t)(i0 + row) * lda + k0 + kc * 8]);
        }
#pragma unroll
        for (int r = 0; r < 4; r++) {
            int idx = t + 256 * r;
            int k = idx >> 4, nc = idx & 15;
            cp16(Bd + k * (HB_LD * 2) + nc * 16,
                 &Bm[(size_t)(k0 + k) * ldb + j0 + nc * 8]);
        }
    };

    float acc[4][4][4];
#pragma unroll
    for (int a = 0; a < 4; a++)
#pragma unroll
        for (int b = 0; b < 4; b++)
#pragma unroll
            for (int c = 0; c < 4; c++) acc[a][b][c] = 0.f;

    const int nIter = K / HBK;
    load_stage(0, 0);
    cp_commit();

    const int aRow = ln & 15, aCol = (ln >> 4) * 8;
    const int bRow = (ln & 7) + ((ln >> 4) << 3), bCol8 = ((ln >> 3) & 1) * 8;

    for (int it = 0; it < nIter; it++) {
        cp_wait<0>();
        __syncthreads();
        if (it + 1 < nIter) load_stage((it + 1) & 1, (it + 1) * HBK);
        cp_commit();

        const char* Ac = smc + (it & 1) * H_STG;
        const char* Bc = Ac + H_ABYTES;

#pragma unroll
        for (int ks = 0; ks < 4; ks++) {
            int kk = ks * 16;
            unsigned bf[4][2];
#pragma unroll
            for (int p = 0; p < 2; p++) {
                unsigned r0, r1, r2, r3;
                ldsm_x4t(r0, r1, r2, r3,
                         Bc + ((kk + bRow) * HB_LD + wc * 32 + p * 16 + bCol8) * 2);
                bf[p * 2][0] = r0; bf[p * 2][1] = r2;
                bf[p * 2 + 1][0] = r1; bf[p * 2 + 1][1] = r3;
            }
#pragma unroll
            for (int mi = 0; mi < 4; mi++) {
                unsigned a0, a1, a2, a3;
                ldsm_x4(a0, a1, a2, a3,
                        Ac + ((wr * 64 + mi * 16 + aRow) * HA_LD + kk + aCol) * 2);
#pragma unroll
                for (int ni = 0; ni < 4; ni++)
                    mma_f16(acc[mi][ni][0], acc[mi][ni][1], acc[mi][ni][2], acc[mi][ni][3],
                            a0, a1, a2, a3, bf[ni][0], bf[ni][1]);
            }
        }
    }

    // ---- epilogue ----
#pragma unroll
    for (int mi = 0; mi < 4; mi++) {
        int r0 = i0 + wr * 64 + mi * 16 + (ln >> 2);
        int r1 = r0 + 8;
        float bv0 = bias ? bias[r0] : 0.f;
        float bv1 = bias ? bias[r1] : 0.f;
#pragma unroll
        for (int ni = 0; ni < 4; ni++) {
            int c0 = j0 + wc * 32 + ni * 8 + 2 * (ln & 3);
            float v00 = acc[mi][ni][0] + bv0;
            float v01 = acc[mi][ni][1] + bv0;
            float v10 = acc[mi][ni][2] + bv1;
            float v11 = acc[mi][ni][3] + bv1;
            if (HOUT) {
                __half* Cm = (__half*)Cv + z * sCi;
                *(__half2*)&Cm[(size_t)r0 * ldc + c0] = __floats2half2_rn(v00, v01);
                *(__half2*)&Cm[(size_t)r1 * ldc + c0] = __floats2half2_rn(v10, v11);
            } else {
                float* Cm = (float*)Cv + z * sCi;
                if (res) {
                    float2 r0v = *(const float2*)&res[(size_t)r0 * ldc + c0];
                    float2 r1v = *(const float2*)&res[(size_t)r1 * ldc + c0];
                    v00 += r0v.x; v01 += r0v.y;
                    v10 += r1v.x; v11 += r1v.y;
                }
                *(float2*)&Cm[(size_t)r0 * ldc + c0] = make_float2(v00, v01);
                *(float2*)&Cm[(size_t)r1 * ldc + c0] = make_float2(v10, v11);
            }
        }
    }
}

// ---------------- fused flash attention: mbarrier ring + QK/softmax pipelining ----------------
#define QTL 128
#define MTL 64
#define FQ_LD 72
#define FK_LD 72
#define FQ_BYTES (QTL * FQ_LD * 2)            // 18432
#define FK_BYTES (MTL * FK_LD * 2)            // 9216
#define FSTG 4
#define FA_SMEM (FQ_BYTES + FSTG * 2 * FK_BYTES)   // 92160

__global__ __launch_bounds__(256, 2)
void flash_attn(const __half* __restrict__ qkv, __half* __restrict__ ao) {
    extern __shared__ __align__(16) char smc[];
    __shared__ __align__(8) unsigned long long bars[2 * FSTG];
    __half* Qs = (__half*)smc;

    const int t = threadIdx.x;
    const int w = t >> 5, ln = t & 31;
    const int r = ln >> 2, j = ln & 3;
    const int bh = blockIdx.y;
    const int b = bh >> 3, h = bh & 7;
    const int q0 = blockIdx.x * QTL;

    const __half* Qp = qkv + (size_t)b * 3 * CC * NN + (size_t)h * HD * NN;
    const __half* Kp = Qp + (size_t)CC * NN;
    const __half* Vp = Qp + 2 * (size_t)CC * NN;

    const unsigned fullB  = smem_u32(&bars[0]);
    const unsigned emptyB = smem_u32(&bars[FSTG]);

    if (t == 0) {
#pragma unroll
        for (int s = 0; s < FSTG; s++) {
            MBAR_INIT(fullB  + s * 8, 256);
            MBAR_INIT(emptyB + s * 8, 256);
        }
    }
    __syncthreads();

    auto load_kv = [&](int st, int mo) {
        char* Ks = smc + FQ_BYTES + st * 2 * FK_BYTES;
        char* Vs = Ks + FK_BYTES;
#pragma unroll
        for (int rr = 0; rr < 2; rr++) {
            int idx = t + 256 * rr;
            int c = idx >> 3, mq = idx & 7;
            cp16(Ks + (c * FK_LD + mq * 8) * 2, &Kp[(size_t)c * NN + mo + mq * 8]);
            cp16(Vs + (c * FK_LD + mq * 8) * 2, &Vp[(size_t)c * NN + mo + mq * 8]);
        }
        cp_arrive(fullB + st * 8);
    };

    load_kv(0, 0);
    load_kv(1, MTL);

    const float QSCALE = 0.125f * 1.44269504f;
    for (int idx = t; idx < QTL * HD; idx += 256) {
        int q = idx & (QTL - 1), c = idx >> 7;
        float f = __half2float(Qp[(size_t)c * NN + q0 + q]) * QSCALE;
        Qs[q * FQ_LD + c] = __float2half_rn(f);
    }
    __syncthreads();

    float o[8][4];
#pragma unroll
    for (int a = 0; a < 8; a++)
#pragma unroll
        for (int bq = 0; bq < 4; bq++) o[a][bq] = 0.f;
    float m0v = -CUDART_INF_F, m1v = -CUDART_INF_F;
    float l0 = 0.f, l1 = 0.f;

    const int aRow = ln & 15, aCol = (ln >> 4) * 8;
    const int bRow = (ln & 7) + ((ln >> 4) << 3), bCol8 = ((ln >> 3) & 1) * 8;
    const int nIt = NN / MTL;

    float s[8][4];
    // QK of a given stage into s
    auto qk = [&](int st) {
#pragma unroll
        for (int a = 0; a < 8; a++)
#pragma unroll
            for (int bq = 0; bq < 4; bq++) s[a][bq] = 0.f;
        const char* Kc = smc + FQ_BYTES + st * 2 * FK_BYTES;
#pragma unroll
        for (int kf = 0; kf < 4; kf++) {
            unsigned a0, a1, a2, a3;
            ldsm_x4(a0, a1, a2, a3,
                    (const char*)Qs + ((w * 16 + aRow) * FQ_LD + kf * 16 + aCol) * 2);
#pragma unroll
            for (int mp = 0; mp < 4; mp++) {
                unsigned r0, r1, r2, r3;
                ldsm_x4t(r0, r1, r2, r3,
                         Kc + ((kf * 16 + bRow) * FK_LD + mp * 16 + bCol8) * 2);
                mma_f16(s[2*mp][0], s[2*mp][1], s[2*mp][2], s[2*mp][3],
                        a0, a1, a2, a3, r0, r2);
                mma_f16(s[2*mp+1][0], s[2*mp+1][1], s[2*mp+1][2], s[2*mp+1][3],
                        a0, a1, a2, a3, r1, r3);
            }
        }
    };

    // prologue: QK(0)
    MBAR_WAIT(fullB + 0, 0);
    qk(0);

    int pS = 2, pPh = 1;      // producer cursor
    int nS = 1, nPh = 0;      // next-full consumer cursor (stage it+1)
    int eS = 0;               // empty-arrival cursor (stage it)

    for (int it = 0; it < nIt; it++) {
        // ---- softmax(it): s -> pa, al; s dies ----
        float tm0 = -CUDART_INF_F, tm1 = -CUDART_INF_F;
#pragma unroll
        for (int ni = 0; ni < 8; ni++) {
            tm0 = fmaxf(tm0, fmaxf(s[ni][0], s[ni][1]));
            tm1 = fmaxf(tm1, fmaxf(s[ni][2], s[ni][3]));
        }
        tm0 = fmaxf(tm0, __shfl_xor_sync(0xffffffffu, tm0, 1));
        tm0 = fmaxf(tm0, __shfl_xor_sync(0xffffffffu, tm0, 2));
        tm1 = fmaxf(tm1, __shfl_xor_sync(0xffffffffu, tm1, 1));
        tm1 = fmaxf(tm1, __shfl_xor_sync(0xffffffffu, tm1, 2));

        float mn0 = fmaxf(m0v, tm0), mn1 = fmaxf(m1v, tm1);
        float al0 = exp2f(m0v - mn0), al1 = exp2f(m1v - mn1);
        m0v = mn0; m1v = mn1;

        unsigned mh0 = packh2(mn0, mn0);
        unsigned mh1 = packh2(mn1, mn1);
        unsigned pa[4][4];
        float rs0 = 0.f, rs1 = 0.f;
#pragma unroll
        for (int g = 0; g < 4; g++) {
            unsigned p00 = h2exp2(hsub2(packh2(s[2*g][0],   s[2*g][1]),   mh0));
            unsigned p01 = h2exp2(hsub2(packh2(s[2*g][2],   s[2*g][3]),   mh1));
            unsigned p10 = h2exp2(hsub2(packh2(s[2*g+1][0], s[2*g+1][1]), mh0));
            unsigned p11 = h2exp2(hsub2(packh2(s[2*g+1][2], s[2*g+1][3]), mh1));
            pa[g][0] = p00; pa[g][1] = p01; pa[g][2] = p10; pa[g][3] = p11;
            rs0 += h2sum(hadd2(p00, p10));
            rs1 += h2sum(hadd2(p01, p11));
        }
        rs0 += __shfl_xor_sync(0xffffffffu, rs0, 1);
        rs0 += __shfl_xor_sync(0xffffffffu, rs0, 2);
        rs1 += __shfl_xor_sync(0xffffffffu, rs1, 1);
        rs1 += __shfl_xor_sync(0xffffffffu, rs1, 2);
        l0 = l0 * al0 + rs0;
        l1 = l1 * al1 + rs1;

        // ---- producer: prefetch stage it+2 ----
        if (it + 2 < nIt) {
            MBAR_WAIT(emptyB + pS * 8, pPh);
            load_kv(pS, (it + 2) * MTL);
            if (++pS == FSTG) { pS = 0; pPh ^= 1; }
        }

        // ---- QK(it+1) into dead s regs: independent HMMA overlapping softmax ----
        if (it + 1 < nIt) {
            MBAR_WAIT(fullB + nS * 8, nPh);
            qk(nS);
            if (++nS == FSTG) { nS = 0; nPh ^= 1; }
        }

        // ---- rescale + PV(it) ----
#pragma unroll
        for (int no = 0; no < 8; no++) {
            o[no][0] *= al0; o[no][1] *= al0;
            o[no][2] *= al1; o[no][3] *= al1;
        }
        const char* Vc = smc + FQ_BYTES + eS * 2 * FK_BYTES + FK_BYTES;
#pragma unroll
        for (int g = 0; g < 4; g++) {
#pragma unroll
            for (int np = 0; np < 4; np++) {
                unsigned r0, r1, r2, r3;
                ldsm_x4(r0, r1, r2, r3,
                        Vc + ((np * 16 + aRow) * FK_LD + g * 16 + aCol) * 2);
                mma_f16(o[2*np][0], o[2*np][1], o[2*np][2], o[2*np][3],
                        pa[g][0], pa[g][1], pa[g][2], pa[g][3], r0, r2);
                mma_f16(o[2*np+1][0], o[2*np+1][1], o[2*np+1][2], o[2*np+1][3],
                        pa[g][0], pa[g][1], pa[g][2], pa[g][3], r1, r3);
            }
        }

        MBAR_ARRIVE(emptyB + eS * 8);
        eS = (eS + 1) & (FSTG - 1);
    }

    // ---- epilogue ----
    float inv0 = 1.f / l0, inv1 = 1.f / l1;
    __half* aop = ao + (size_t)b * CC * NN + (size_t)h * HD * NN;
    const int qrow = w * 16 + r;
#pragma unroll
    for (int no = 0; no < 8; no++) {
        int hd0 = no * 8 + 2 * j;
        aop[(size_t)hd0 * NN + q0 + qrow]           = __float2half_rn(o[no][0] * inv0);
        aop[(size_t)(hd0 + 1) * NN + q0 + qrow]     = __float2half_rn(o[no][1] * inv0);
        aop[(size_t)hd0 * NN + q0 + qrow + 8]       = __float2half_rn(o[no][2] * inv1);
        aop[(size_t)(hd0 + 1) * NN + q0 + qrow + 8] = __float2half_rn(o[no][3] * inv1);
    }
}

// ---------------- launch ----------------
extern "C" void kernel_launch(void* const* d_in, const int* in_sizes, int n_in,
                              void* d_out, int out_size) {
    (void)in_sizes; (void)n_in; (void)out_size;
    const float* x  = (const float*)d_in[0];
    const float* nw = (const float*)d_in[1];
    const float* nb = (const float*)d_in[2];
    const float* qw = (const float*)d_in[3];
    const float* qb = (const float*)d_in[4];
    const float* pw = (const float*)d_in[5];
    const float* pb = (const float*)d_in[6];
    float* out = (float*)d_out;

    __half *xn16, *qkv16, *ao16, *qw16, *pw16;
    cudaGetSymbolAddress((void**)&xn16,  g_xn16);
    cudaGetSymbolAddress((void**)&qkv16, g_qkv16);
    cudaGetSymbolAddress((void**)&ao16,  g_ao16);
    cudaGetSymbolAddress((void**)&qw16,  g_qw16);
    cudaGetSymbolAddress((void**)&pw16,  g_pw16);

    const long long bCN  = (long long)CC * NN;
    const long long b3CN = 3LL * CC * NN;

    cudaFuncSetAttribute(hgemm<true>,  cudaFuncAttributeMaxDynamicSharedMemorySize, H_SMEM);
    cudaFuncSetAttribute(hgemm<false>, cudaFuncAttributeMaxDynamicSharedMemorySize, H_SMEM);
    cudaFuncSetAttribute(flash_attn,   cudaFuncAttributeMaxDynamicSharedMemorySize, FA_SMEM);

    // 0) weights f32 -> f16
    convert_weights<<<(QW4 + PW4 + 255) / 256, 256>>>(qw, pw, qw16, pw16);

    // 1) GroupNorm -> fp16 xn
    groupnorm_kernel<<<BB * NGROUPS, 512>>>(x, nw, nb, xn16);

    // 2) QKV (fp16 out)
    hgemm<true><<<dim3(12, 8, BB), 256, H_SMEM>>>(
        qw16, xn16, qkv16, CC, CC, NN, NN, bCN, b3CN, qb, nullptr, 0);

    // 3) Fused attention (fp16 in/out)
    flash_attn<<<dim3(NN / QTL, BB * NHEADS), 256, FA_SMEM>>>(qkv16, ao16);

    // 4) Proj + bias + residual (f32 out)
    hgemm<false><<<dim3(4, 8, BB), 256, H_SMEM>>>(
        pw16, ao16, out, CC, CC, NN, NN, bCN, bCN, pb, x, bCN);
}

// round 16
// speedup vs baseline: 1.0337x; 1.0337x over previous
#include <cuda_runtime.h>
#include <cuda_fp16.h>
#include <cstddef>
#include <cstdint>
#include <math_constants.h>

#define BB 8
#define CC 512
#define NHEADS 8
#define HD 64
#define NN 1024
#define NGROUPS 32
#define GSIZE ((CC / NGROUPS) * NN)   // 16384
#define EPSV 1e-5f

// ---------------- scratch ----------------
__device__ __half g_xn16[BB * CC * NN];        // 8 MB
__device__ __half g_qkv16[BB * 3 * CC * NN];   // 24 MB
__device__ __half g_ao16[BB * CC * NN];        // 8 MB
__device__ __half g_qw16[3 * CC * CC];         // 1.5 MB
__device__ __half g_pw16[CC * CC];             // 0.5 MB

// ---------------- helpers ----------------
__device__ __forceinline__ unsigned smem_u32(const void* p) {
    return (unsigned)__cvta_generic_to_shared(p);
}
__device__ __forceinline__ void cp16(void* sdst, const void* gsrc) {
    asm volatile("cp.async.cg.shared.global [%0], [%1], 16;\n"
                 :: "r"(smem_u32(sdst)), "l"(gsrc));
}
__device__ __forceinline__ void cp_commit() {
    asm volatile("cp.async.commit_group;\n");
}
template <int N>
__device__ __forceinline__ void cp_wait() {
    asm volatile("cp.async.wait_group %0;\n" :: "n"(N));
}
__device__ __forceinline__ void cp_arrive(unsigned mbar) {
    asm volatile("cp.async.mbarrier.arrive.noinc.shared.b64 [%0];\n"
                 :: "r"(mbar) : "memory");
}
#define MBAR_INIT(addr, cnt) \
    asm volatile("mbarrier.init.shared.b64 [%0], %1;" :: "r"(addr), "r"(cnt) : "memory")
#define MBAR_ARRIVE(addr) \
    asm volatile("mbarrier.arrive.shared.b64 _, [%0];" :: "r"(addr) : "memory")
#define MBAR_WAIT(addr, par) do {                                              \
    asm volatile("{\n\t.reg .pred P1;\n\t"                                     \
        "WAIT_%=:\n\t"                                                          \
        "mbarrier.try_wait.parity.acquire.cta.shared::cta.b64 P1, [%0], %1, 0x989680;\n\t" \
        "@P1 bra.uni DONE_%=;\n\t"                                              \
        "bra.uni WAIT_%=;\n\t"                                                  \
        "DONE_%=:\n\t}"                                                         \
        :: "r"(addr), "r"(par) : "memory");                                     \
} while (0)

__device__ __forceinline__ void ldsm_x4(unsigned& d0, unsigned& d1,
                                        unsigned& d2, unsigned& d3, const void* p) {
    asm volatile("ldmatrix.sync.aligned.m8n8.x4.shared.b16 {%0,%1,%2,%3}, [%4];\n"
                 : "=r"(d0), "=r"(d1), "=r"(d2), "=r"(d3) : "r"(smem_u32(p)));
}
__device__ __forceinline__ void ldsm_x4t(unsigned& d0, unsigned& d1,
                                         unsigned& d2, unsigned& d3, const void* p) {
    asm volatile("ldmatrix.sync.aligned.m8n8.x4.trans.shared.b16 {%0,%1,%2,%3}, [%4];\n"
                 : "=r"(d0), "=r"(d1), "=r"(d2), "=r"(d3) : "r"(smem_u32(p)));
}
__device__ __forceinline__ void mma_f16(float& c0, float& c1, float& c2, float& c3,
                                        unsigned a0, unsigned a1, unsigned a2, unsigned a3,
                                        unsigned b0, unsigned b1) {
    asm volatile(
        "mma.sync.aligned.m16n8k16.row.col.f32.f16.f16.f32 "
        "{%0,%1,%2,%3}, {%4,%5,%6,%7}, {%8,%9}, {%0,%1,%2,%3};\n"
        : "+f"(c0), "+f"(c1), "+f"(c2), "+f"(c3)
        : "r"(a0), "r"(a1), "r"(a2), "r"(a3), "r"(b0), "r"(b1));
}
__device__ __forceinline__ unsigned packh2(float lo, float hi) {
    unsigned u;
    asm("cvt.rn.f16x2.f32 %0, %2, %1;" : "=r"(u) : "f"(lo), "f"(hi));
    return u;
}
__device__ __forceinline__ unsigned h2exp2(unsigned x) {
    unsigned r;
    asm("ex2.approx.f16x2 %0, %1;" : "=r"(r) : "r"(x));
    return r;
}
__device__ __forceinline__ unsigned hsub2(unsigned a, unsigned b) {
    unsigned r;
    asm("sub.f16x2 %0, %1, %2;" : "=r"(r) : "r"(a), "r"(b));
    return r;
}
__device__ __forceinline__ unsigned hadd2(unsigned a, unsigned b) {
    unsigned r;
    asm("add.f16x2 %0, %1, %2;" : "=r"(r) : "r"(a), "r"(b));
    return r;
}
__device__ __forceinline__ float h2sum(unsigned x) {
    __half2 h = *(__half2*)&x;
    float2 f = __half22float2(h);
    return f.x + f.y;
}

// ---------------- prep: groupnorm (blocks 0..255) + weight convert (blocks 256..511) ----------------
#define QW4 (3 * CC * CC / 4)                 // 196608 float4s
#define PW4 (CC * CC / 4)                     // 65536
#define PREP_GN_BLOCKS (BB * NGROUPS)         // 256
#define PREP_CV_BLOCKS ((QW4 + PW4) / 1024)   // 256
__global__ __launch_bounds__(1024)
void prep_kernel(const float* __restrict__ x,
                 const float* __restrict__ w,
                 const float* __restrict__ bch,
                 __half* __restrict__ xn,
                 const float* __restrict__ qw, const float* __restrict__ pw,
                 __half* __restrict__ qw16, __half* __restrict__ pw16) {
    if (blockIdx.x >= PREP_GN_BLOCKS) {
        // ---- weight f32 -> f16 ----
        int i = (blockIdx.x - PREP_GN_BLOCKS) * 1024 + threadIdx.x;
        const float* src;
        __half* dst;
        int k;
        if (i < QW4) { src = qw; dst = qw16; k = i; }
        else { src = pw; dst = pw16; k = i - QW4; }
        float4 v = *(const float4*)&src[k * 4];
        __half2* o = (__half2*)&dst[k * 4];
        o[0] = __floats2half2_rn(v.x, v.y);
        o[1] = __floats2half2_rn(v.z, v.w);
        return;
    }
    // ---- GroupNorm ----
    int bg = blockIdx.x;
    const float* xp = x + (size_t)bg * GSIZE;
    __half* op = xn + (size_t)bg * GSIZE;
    int t = threadIdx.x;

    float s = 0.f, s2 = 0.f;
    for (int i = t; i < GSIZE / 4; i += blockDim.x) {
        float4 v = *(const float4*)&xp[i * 4];
        s  += v.x + v.y + v.z + v.w;
        s2 += v.x * v.x + v.y * v.y + v.z * v.z + v.w * v.w;
    }
    __shared__ float rs[32], rs2[32];
    for (int o = 16; o; o >>= 1) {
        s  += __shfl_xor_sync(0xffffffffu, s,  o);
        s2 += __shfl_xor_sync(0xffffffffu, s2, o);
    }
    if ((t & 31) == 0) { rs[t >> 5] = s; rs2[t >> 5] = s2; }
    __syncthreads();
    if (t < 32) {
        int nw = blockDim.x >> 5;
        float a  = (t < nw) ? rs[t]  : 0.f;
        float a2 = (t < nw) ? rs2[t] : 0.f;
        for (int o = 16; o; o >>= 1) {
            a  += __shfl_xor_sync(0xffffffffu, a,  o);
            a2 += __shfl_xor_sync(0xffffffffu, a2, o);
        }
        if (t == 0) {
            float mean = a / (float)GSIZE;
            float var  = a2 / (float)GSIZE - mean * mean;
            rs[0]  = mean;
            rs2[0] = rsqrtf(var + EPSV);
        }
    }
    __syncthreads();
    float mean = rs[0], rstd = rs2[0];
    int c0 = (bg % NGROUPS) * (CC / NGROUPS);
    for (int i = t; i < GSIZE / 4; i += blockDim.x) {
        int c = c0 + (i * 4) / NN;
        float sc = rstd * w[c], bc = bch[c] - mean * sc;
        float4 v = *(const float4*)&xp[i * 4];
        __half2* o = (__half2*)&op[i * 4];
        o[0] = __floats2half2_rn(v.x * sc + bc, v.y * sc + bc);
        o[1] = __floats2half2_rn(v.z * sc + bc, v.w * sc + bc);
    }
}

// ---------------- fp16 HGEMM, BK=64, 2-stage, one sync/iter ----------------
#define HBK 64
#define HA_LD 72
#define HB_LD 136
#define H_ABYTES (128 * HA_LD * 2)       // 18432
#define H_BBYTES (HBK * HB_LD * 2)       // 17408
#define H_STG (H_ABYTES + H_BBYTES)      // 35840
#define H_SMEM (2 * H_STG)               // 71680

template <bool HOUT>
__global__ __launch_bounds__(256, 2)
void hgemm(const __half* __restrict__ A,
           const __half* __restrict__ Bm,
           void* __restrict__ Cv,
           int K, int lda, int ldb, int ldc,
           long long sBi, long long sCi,
           const float* __restrict__ bias,
           const float* __restrict__ res,
           long long sRi) {
    int z = blockIdx.z;
    Bm += z * sBi;
    if (res) res += z * sRi;

    extern __shared__ __align__(16) char smc[];
    const int t  = threadIdx.x;
    const int w  = t >> 5, ln = t & 31;
    const int wr = w >> 2, wc = w & 3;
    const int i0 = blockIdx.x * 128, j0 = blockIdx.y * 128;

    auto load_stage = [&](int st, int k0) {
        char* Ad = smc + st * H_STG;
        char* Bd = Ad + H_ABYTES;
#pragma unroll
        for (int r = 0; r < 4; r++) {
            int idx = t + 256 * r;
            int row = idx >> 3, kc = idx & 7;
            cp16(Ad + row * (HA_LD * 2) + kc * 16,
                 &A[(size_t)(i0 + row) * lda + k0 + kc * 8]);
        }
#pragma unroll
        for (int r = 0; r < 4; r++) {
            int idx = t + 256 * r;
            int k = idx >> 4, nc = idx & 15;
            cp16(Bd + k * (HB_LD * 2) + nc * 16,
                 &Bm[(size_t)(k0 + k) * ldb + j0 + nc * 8]);
        }
    };

    float acc[4][4][4];
#pragma unroll
    for (int a = 0; a < 4; a++)
#pragma unroll
        for (int b = 0; b < 4; b++)
#pragma unroll
            for (int c = 0; c < 4; c++) acc[a][b][c] = 0.f;

    const int nIter = K / HBK;
    load_stage(0, 0);
    cp_commit();

    const int aRow = ln & 15, aCol = (ln >> 4) * 8;
    const int bRow = (ln & 7) + ((ln >> 4) << 3), bCol8 = ((ln >> 3) & 1) * 8;

    for (int it = 0; it < nIter; it++) {
        cp_wait<0>();
        __syncthreads();
        if (it + 1 < nIter) load_stage((it + 1) & 1, (it + 1) * HBK);
        cp_commit();

        const char* Ac = smc + (it & 1) * H_STG;
        const char* Bc = Ac + H_ABYTES;

#pragma unroll
        for (int ks = 0; ks < 4; ks++) {
            int kk = ks * 16;
            unsigned bf[4][2];
#pragma unroll
            for (int p = 0; p < 2; p++) {
                unsigned r0, r1, r2, r3;
                ldsm_x4t(r0, r1, r2, r3,
                         Bc + ((kk + bRow) * HB_LD + wc * 32 + p * 16 + bCol8) * 2);
                bf[p * 2][0] = r0; bf[p * 2][1] = r2;
                bf[p * 2 + 1][0] = r1; bf[p * 2 + 1][1] = r3;
            }
#pragma unroll
            for (int mi = 0; mi < 4; mi++) {
                unsigned a0, a1, a2, a3;
                ldsm_x4(a0, a1, a2, a3,
                        Ac + ((wr * 64 + mi * 16 + aRow) * HA_LD + kk + aCol) * 2);
#pragma unroll
                for (int ni = 0; ni < 4; ni++)
                    mma_f16(acc[mi][ni][0], acc[mi][ni][1], acc[mi][ni][2], acc[mi][ni][3],
                            a0, a1, a2, a3, bf[ni][0], bf[ni][1]);
            }
        }
    }

    // ---- epilogue ----
#pragma unroll
    for (int mi = 0; mi < 4; mi++) {
        int r0 = i0 + wr * 64 + mi * 16 + (ln >> 2);
        int r1 = r0 + 8;
        float bv0 = bias ? bias[r0] : 0.f;
        float bv1 = bias ? bias[r1] : 0.f;
#pragma unroll
        for (int ni = 0; ni < 4; ni++) {
            int c0 = j0 + wc * 32 + ni * 8 + 2 * (ln & 3);
            float v00 = acc[mi][ni][0] + bv0;
            float v01 = acc[mi][ni][1] + bv0;
            float v10 = acc[mi][ni][2] + bv1;
            float v11 = acc[mi][ni][3] + bv1;
            if (HOUT) {
                __half* Cm = (__half*)Cv + z * sCi;
                *(__half2*)&Cm[(size_t)r0 * ldc + c0] = __floats2half2_rn(v00, v01);
                *(__half2*)&Cm[(size_t)r1 * ldc + c0] = __floats2half2_rn(v10, v11);
            } else {
                float* Cm = (float*)Cv + z * sCi;
                if (res) {
                    float2 r0v = *(const float2*)&res[(size_t)r0 * ldc + c0];
                    float2 r1v = *(const float2*)&res[(size_t)r1 * ldc + c0];
                    v00 += r0v.x; v01 += r0v.y;
                    v10 += r1v.x; v11 += r1v.y;
                }
                *(float2*)&Cm[(size_t)r0 * ldc + c0] = make_float2(v00, v01);
                *(float2*)&Cm[(size_t)r1 * ldc + c0] = make_float2(v10, v11);
            }
        }
    }
}

// ---------------- fused flash attention: mbarrier ring (R14 structure) ----------------
#define QTL 128
#define MTL 64
#define FQ_LD 72
#define FK_LD 72
#define FQ_BYTES (QTL * FQ_LD * 2)            // 18432
#define FK_BYTES (MTL * FK_LD * 2)            // 9216
#define FSTG 4
#define FA_SMEM (FQ_BYTES + FSTG * 2 * FK_BYTES)   // 92160

__global__ __launch_bounds__(256, 2)
void flash_attn(const __half* __restrict__ qkv, __half* __restrict__ ao) {
    extern __shared__ __align__(16) char smc[];
    __shared__ __align__(8) unsigned long long bars[2 * FSTG];
    __half* Qs = (__half*)smc;

    const int t = threadIdx.x;
    const int w = t >> 5, ln = t & 31;
    const int r = ln >> 2, j = ln & 3;
    const int bh = blockIdx.y;
    const int b = bh >> 3, h = bh & 7;
    const int q0 = blockIdx.x * QTL;

    const __half* Qp = qkv + (size_t)b * 3 * CC * NN + (size_t)h * HD * NN;
    const __half* Kp = Qp + (size_t)CC * NN;
    const __half* Vp = Qp + 2 * (size_t)CC * NN;

    const unsigned fullB  = smem_u32(&bars[0]);
    const unsigned emptyB = smem_u32(&bars[FSTG]);

    if (t == 0) {
#pragma unroll
        for (int s = 0; s < FSTG; s++) {
            MBAR_INIT(fullB  + s * 8, 256);
            MBAR_INIT(emptyB + s * 8, 256);
        }
    }
    __syncthreads();

    auto load_kv = [&](int st, int mo) {
        char* Ks = smc + FQ_BYTES + st * 2 * FK_BYTES;
        char* Vs = Ks + FK_BYTES;
#pragma unroll
        for (int rr = 0; rr < 2; rr++) {
            int idx = t + 256 * rr;
            int c = idx >> 3, mq = idx & 7;
            cp16(Ks + (c * FK_LD + mq * 8) * 2, &Kp[(size_t)c * NN + mo + mq * 8]);
            cp16(Vs + (c * FK_LD + mq * 8) * 2, &Vp[(size_t)c * NN + mo + mq * 8]);
        }
        cp_arrive(fullB + st * 8);
    };

    load_kv(0, 0);
    load_kv(1, MTL);

    const float QSCALE = 0.125f * 1.44269504f;
    for (int idx = t; idx < QTL * HD; idx += 256) {
        int q = idx & (QTL - 1), c = idx >> 7;
        float f = __half2float(Qp[(size_t)c * NN + q0 + q]) * QSCALE;
        Qs[q * FQ_LD + c] = __float2half_rn(f);
    }
    __syncthreads();

    float o[8][4];
#pragma unroll
    for (int a = 0; a < 8; a++)
#pragma unroll
        for (int bq = 0; bq < 4; bq++) o[a][bq] = 0.f;
    float m0v = -CUDART_INF_F, m1v = -CUDART_INF_F;
    float l0 = 0.f, l1 = 0.f;

    const int aRow = ln & 15, aCol = (ln >> 4) * 8;
    const int bRow = (ln & 7) + ((ln >> 4) << 3), bCol8 = ((ln >> 3) & 1) * 8;
    const int nIt = NN / MTL;

    int pS = 2, pPh = 1;
    int cS = 0, cPh = 0;

    for (int it = 0; it < nIt; it++) {
        if (it + 2 < nIt) {
            MBAR_WAIT(emptyB + pS * 8, pPh);
            load_kv(pS, (it + 2) * MTL);
            if (++pS == FSTG) { pS = 0; pPh ^= 1; }
        }
        MBAR_WAIT(fullB + cS * 8, cPh);
        const char* Kc = smc + FQ_BYTES + cS * 2 * FK_BYTES;
        const char* Vc = Kc + FK_BYTES;

        // ---- S = Q K^T (log2-scaled) ----
        float s[8][4];
#pragma unroll
        for (int a = 0; a < 8; a++)
#pragma unroll
            for (int bq = 0; bq < 4; bq++) s[a][bq] = 0.f;

#pragma unroll
        for (int kf = 0; kf < 4; kf++) {
            unsigned a0, a1, a2, a3;
            ldsm_x4(a0, a1, a2, a3,
                    (const char*)Qs + ((w * 16 + aRow) * FQ_LD + kf * 16 + aCol) * 2);
#pragma unroll
            for (int mp = 0; mp < 4; mp++) {
                unsigned r0, r1, r2, r3;
                ldsm_x4t(r0, r1, r2, r3,
                         Kc + ((kf * 16 + bRow) * FK_LD + mp * 16 + bCol8) * 2);
                mma_f16(s[2*mp][0], s[2*mp][1], s[2*mp][2], s[2*mp][3],
                        a0, a1, a2, a3, r0, r2);
                mma_f16(s[2*mp+1][0], s[2*mp+1][1], s[2*mp+1][2], s[2*mp+1][3],
                        a0, a1, a2, a3, r1, r3);
            }
        }

        // ---- online softmax, log2 domain ----
        float tm0 = -CUDART_INF_F, tm1 = -CUDART_INF_F;
#pragma unroll
        for (int ni = 0; ni < 8; ni++) {
            tm0 = fmaxf(tm0, fmaxf(s[ni][0], s[ni][1]));
            tm1 = fmaxf(tm1, fmaxf(s[ni][2], s[ni][3]));
        }
        tm0 = fmaxf(tm0, __shfl_xor_sync(0xffffffffu, tm0, 1));
        tm0 = fmaxf(tm0, __shfl_xor_sync(0xffffffffu, tm0, 2));
        tm1 = fmaxf(tm1, __shfl_xor_sync(0xffffffffu, tm1, 1));
        tm1 = fmaxf(tm1, __shfl_xor_sync(0xffffffffu, tm1, 2));

        float mn0 = fmaxf(m0v, tm0), mn1 = fmaxf(m1v, tm1);
        float al0 = exp2f(m0v - mn0), al1 = exp2f(m1v - mn1);
        m0v = mn0; m1v = mn1;

        unsigned mh0 = packh2(mn0, mn0);
        unsigned mh1 = packh2(mn1, mn1);
        unsigned pa[4][4];
        float rs0 = 0.f, rs1 = 0.f;
#pragma unroll
        for (int g = 0; g < 4; g++) {
            unsigned p00 = h2exp2(hsub2(packh2(s[2*g][0],   s[2*g][1]),   mh0));
            unsigned p01 = h2exp2(hsub2(packh2(s[2*g][2],   s[2*g][3]),   mh1));
            unsigned p10 = h2exp2(hsub2(packh2(s[2*g+1][0], s[2*g+1][1]), mh0));
            unsigned p11 = h2exp2(hsub2(packh2(s[2*g+1][2], s[2*g+1][3]), mh1));
            pa[g][0] = p00; pa[g][1] = p01; pa[g][2] = p10; pa[g][3] = p11;
            rs0 += h2sum(hadd2(p00, p10));
            rs1 += h2sum(hadd2(p01, p11));
        }
        rs0 += __shfl_xor_sync(0xffffffffu, rs0, 1);
        rs0 += __shfl_xor_sync(0xffffffffu, rs0, 2);
        rs1 += __shfl_xor_sync(0xffffffffu, rs1, 1);
        rs1 += __shfl_xor_sync(0xffffffffu, rs1, 2);
        l0 = l0 * al0 + rs0;
        l1 = l1 * al1 + rs1;

#pragma unroll
        for (int no = 0; no < 8; no++) {
            o[no][0] *= al0; o[no][1] *= al0;
            o[no][2] *= al1; o[no][3] *= al1;
        }

        // ---- O += P V^T ----
#pragma unroll
        for (int g = 0; g < 4; g++) {
#pragma unroll
            for (int np = 0; np < 4; np++) {
                unsigned r0, r1, r2, r3;
                ldsm_x4(r0, r1, r2, r3,
                        Vc + ((np * 16 + aRow) * FK_LD + g * 16 + aCol) * 2);
                mma_f16(o[2*np][0], o[2*np][1], o[2*np][2], o[2*np][3],
                        pa[g][0], pa[g][1], pa[g][2], pa[g][3], r0, r2);
                mma_f16(o[2*np+1][0], o[2*np+1][1], o[2*np+1][2], o[2*np+1][3],
                        pa[g][0], pa[g][1], pa[g][2], pa[g][3], r1, r3);
            }
        }

        MBAR_ARRIVE(emptyB + cS * 8);
        if (++cS == FSTG) { cS = 0; cPh ^= 1; }
    }

    // ---- epilogue ----
    float inv0 = 1.f / l0, inv1 = 1.f / l1;
    __half* aop = ao + (size_t)b * CC * NN + (size_t)h * HD * NN;
    const int qrow = w * 16 + r;
#pragma unroll
    for (int no = 0; no < 8; no++) {
        int hd0 = no * 8 + 2 * j;
        aop[(size_t)hd0 * NN + q0 + qrow]           = __float2half_rn(o[no][0] * inv0);
        aop[(size_t)(hd0 + 1) * NN + q0 + qrow]     = __float2half_rn(o[no][1] * inv0);
        aop[(size_t)hd0 * NN + q0 + qrow + 8]       = __float2half_rn(o[no][2] * inv1);
        aop[(size_t)(hd0 + 1) * NN + q0 + qrow + 8] = __float2half_rn(o[no][3] * inv1);
    }
}

// ---------------- launch ----------------
extern "C" void kernel_launch(void* const* d_in, const int* in_sizes, int n_in,
                              void* d_out, int out_size) {
    (void)in_sizes; (void)n_in; (void)out_size;
    const float* x  = (const float*)d_in[0];
    const float* nw = (const float*)d_in[1];
    const float* nb = (const float*)d_in[2];
    const float* qw = (const float*)d_in[3];
    const float* qb = (const float*)d_in[4];
    const float* pw = (const float*)d_in[5];
    const float* pb = (const float*)d_in[6];
    float* out = (float*)d_out;

    __half *xn16, *qkv16, *ao16, *qw16, *pw16;
    cudaGetSymbolAddress((void**)&xn16,  g_xn16);
    cudaGetSymbolAddress((void**)&qkv16, g_qkv16);
    cudaGetSymbolAddress((void**)&ao16,  g_ao16);
    cudaGetSymbolAddress((void**)&qw16,  g_qw16);
    cudaGetSymbolAddress((void**)&pw16,  g_pw16);

    const long long bCN  = (long long)CC * NN;
    const long long b3CN = 3LL * CC * NN;

    cudaFuncSetAttribute(hgemm<true>,  cudaFuncAttributeMaxDynamicSharedMemorySize, H_SMEM);
    cudaFuncSetAttribute(hgemm<false>, cudaFuncAttributeMaxDynamicSharedMemorySize, H_SMEM);
    cudaFuncSetAttribute(flash_attn,   cudaFuncAttributeMaxDynamicSharedMemorySize, FA_SMEM);

    // 1) GroupNorm + weight conversion (single launch)
    prep_kernel<<<PREP_GN_BLOCKS + PREP_CV_BLOCKS, 1024>>>(
        x, nw, nb, xn16, qw, pw, qw16, pw16);

    // 2) QKV (fp16 out)
    hgemm<true><<<dim3(12, 8, BB), 256, H_SMEM>>>(
        qw16, xn16, qkv16, CC, CC, NN, NN, bCN, b3CN, qb, nullptr, 0);

    // 3) Fused attention (fp16 in/out)
    flash_attn<<<dim3(NN / QTL, BB * NHEADS), 256, FA_SMEM>>>(qkv16, ao16);

    // 4) Proj + bias + residual (f32 out)
    hgemm<false><<<dim3(4, 8, BB), 256, H_SMEM>>>(
        pw16, ao16, out, CC, CC, NN, NN, bCN, bCN, pb, x, bCN);
}